// round 2
// baseline (speedup 1.0000x reference)
#include <cuda_runtime.h>
#include <math.h>

// Problem shapes (fixed by dataset)
#define B 4
#define S 256
#define C 3
#define H 64
#define K 8

#define NDT 16384   // dist-table entries (global, ~4MB, L2-resident)
#define NA  512     // angle-table entries (shared, 128KB)
#define PI_F 3.14159265358979323846f

// Scratch (allocation-free: __device__ globals)
__device__ float g_rv[B * S * K * 3];     // knn relative vectors r_m = c_nbr - c_i
__device__ float g_blockmax[B];           // per-batch max squared distance
__device__ float g_dtab[NDT * H];         // g_d(x) table
__device__ float g_atab[NA * H];          // g_a(theta) table

// ---------------------------------------------------------------------------
// Kernel B: per-(b,i) kNN (k=8 smallest of sq_i+sq_j-2 dot, stable ties) +
//           per-batch max distance.
// ---------------------------------------------------------------------------
__global__ void knn_kernel(const float* __restrict__ centroid) {
    __shared__ float cx[S], cy[S], cz[S], sq[S];
    __shared__ float redmax[S];
    int b = blockIdx.x;
    int t = threadIdx.x;

    const float* cb = centroid + (size_t)b * S * 3;
    float x = cb[t * 3 + 0];
    float y = cb[t * 3 + 1];
    float z = cb[t * 3 + 2];
    cx[t] = x; cy[t] = y; cz[t] = z;
    sq[t] = x * x + y * y + z * z;
    __syncthreads();

    float cix = cx[t], ciy = cy[t], ciz = cz[t];
    float sqi = sq[t];

    float bd[K];
    int   bi[K];
#pragma unroll
    for (int m = 0; m < K; m++) { bd[m] = 3.4e38f; bi[m] = 0; }

    float lmax = 0.f;
    for (int j = 0; j < S; j++) {
        float d = sqi + sq[j] - 2.f * (cix * cx[j] + ciy * cy[j] + ciz * cz[j]);
        lmax = fmaxf(lmax, d);
        if (d < bd[K - 1]) {
            int p = K - 1;
            while (p > 0 && d < bd[p - 1]) {
                bd[p] = bd[p - 1]; bi[p] = bi[p - 1]; p--;
            }
            bd[p] = d; bi[p] = j;
        }
    }

    redmax[t] = lmax;
    __syncthreads();
    if (t == 0) {
        float m = 0.f;
        for (int k2 = 0; k2 < S; k2++) m = fmaxf(m, redmax[k2]);
        g_blockmax[b] = m;
    }

    // store knn relative vectors
    size_t base = ((size_t)(b * S + t)) * K * 3;
#pragma unroll
    for (int m = 0; m < K; m++) {
        int id = bi[m];
        g_rv[base + m * 3 + 0] = cx[id] - cix;
        g_rv[base + m * 3 + 1] = cy[id] - ciy;
        g_rv[base + m * 3 + 2] = cz[id] - ciz;
    }
}

// ---------------------------------------------------------------------------
// Kernel A: build tables. One warp per table row.
//  row < NDT  -> d-table at x = row * dmax/(NDT-1)  using Wd,bd
//  else       -> a-table at x = (row-NDT) * pi/(NA-1) using Wa,ba
// ---------------------------------------------------------------------------
__global__ void table_kernel(const float* __restrict__ Wd, const float* __restrict__ bd,
                             const float* __restrict__ Wa, const float* __restrict__ ba) {
    int warp = threadIdx.x >> 5;
    int lane = threadIdx.x & 31;
    int row = blockIdx.x * 8 + warp;
    if (row >= NDT + NA) return;

    float dmax = fmaxf(fmaxf(g_blockmax[0], g_blockmax[1]),
                       fmaxf(g_blockmax[2], g_blockmax[3]));

    float x;
    const float* W;
    const float* bias;
    float* tab;
    if (row < NDT) {
        x = (float)row * (dmax / (float)(NDT - 1));
        W = Wd; bias = bd; tab = g_dtab + (size_t)row * H;
    } else {
        int r2 = row - NDT;
        x = (float)r2 * (PI_F / (float)(NA - 1));
        W = Wa; bias = ba; tab = g_atab + (size_t)r2 * H;
    }

    // lane owns frequency f=lane: div_f = exp(-ln(10000)/32 * f)
    float divf = expf(-0.28782313662425572f * (float)lane);
    float sv, cv;
    sincosf(x * divf, &sv, &cv);

    int o0 = 2 * lane, o1 = o0 + 1;
    float acc0 = bias[o0];
    float acc1 = bias[o1];
#pragma unroll
    for (int f = 0; f < 32; f++) {
        float sf = __shfl_sync(0xffffffffu, sv, f);
        float cf = __shfl_sync(0xffffffffu, cv, f);
        acc0 = fmaf(sf, __ldg(&W[o0 * H + 2 * f]), acc0);
        acc0 = fmaf(cf, __ldg(&W[o0 * H + 2 * f + 1]), acc0);
        acc1 = fmaf(sf, __ldg(&W[o1 * H + 2 * f]), acc1);
        acc1 = fmaf(cf, __ldg(&W[o1 * H + 2 * f + 1]), acc1);
    }
    tab[o0] = acc0;
    tab[o1] = acc1;
}

// ---------------------------------------------------------------------------
// fast atan2 for y >= 0, result in [0, pi]. ~1e-6 abs error.
// ---------------------------------------------------------------------------
__device__ __forceinline__ float fast_atan2_pos(float y, float x) {
    float ax = fabsf(x);
    float mn = fminf(ax, y);
    float mx = fmaxf(ax, y);
    float t = __fdividef(mn, fmaxf(mx, 1e-30f));   // 0 when both are 0
    float t2 = t * t;
    float p = fmaf(t2, -0.01172120f, 0.05265332f);
    p = fmaf(t2, p, -0.11643287f);
    p = fmaf(t2, p, 0.19354346f);
    p = fmaf(t2, p, -0.33262347f);
    p = fmaf(t2, p, 0.99997726f);
    float th = t * p;
    th = (y > ax) ? (1.5707963267948966f - th) : th;
    th = (x < 0.f) ? (3.1415926535897931f - th) : th;
    return th;
}

// ---------------------------------------------------------------------------
// Kernel C: main. Grid 256 CTAs x 512 threads; CTA handles 4 consecutive
// (b,i) rows (all within one batch). a-table staged in SMEM; one warp per j,
// 2 outputs per lane (float2), lerp + max over 8 neighbors.
// ---------------------------------------------------------------------------
__global__ __launch_bounds__(512, 1)
void main_kernel(const float* __restrict__ centroid, float* __restrict__ out) {
    extern __shared__ float sm[];
    float* s_atab = sm;               // NA*H = 32768 floats
    float* s_cx = sm + NA * H;        // 256
    float* s_cy = s_cx + S;
    float* s_cz = s_cy + S;
    float* s_sq = s_cz + S;
    float* s_rv = s_sq + S;           // 4 rows * K * 3 = 96

    int tid = threadIdx.x;

    // stage a-table
    {
        float4* dst = (float4*)s_atab;
        const float4* src = (const float4*)g_atab;
        for (int idx = tid; idx < (NA * H) / 4; idx += 512) dst[idx] = src[idx];
    }
    int b = blockIdx.x >> 6;   // 4 rows per CTA, 64 CTAs per batch
    {
        const float* cb = centroid + (size_t)b * S * 3;
        if (tid < S) {
            float x = cb[tid * 3 + 0];
            float y = cb[tid * 3 + 1];
            float z = cb[tid * 3 + 2];
            s_cx[tid] = x; s_cy[tid] = y; s_cz[tid] = z;
            s_sq[tid] = x * x + y * y + z * z;
        }
        if (tid < 4 * K * 3) {
            s_rv[tid] = g_rv[(size_t)blockIdx.x * (4 * K * 3) + tid];
        }
    }
    float dmax = fmaxf(fmaxf(g_blockmax[0], g_blockmax[1]),
                       fmaxf(g_blockmax[2], g_blockmax[3]));
    float dscale = (float)(NDT - 1) / dmax;
    const float ascale = (float)(NA - 1) / PI_F;
    __syncthreads();

    int warp = tid >> 5;
    int lane = tid & 31;

    for (int rr = 0; rr < 4; rr++) {
        int row = blockIdx.x * 4 + rr;     // global (b*S+i)
        int i = row & (S - 1);
        float cix = s_cx[i], ciy = s_cy[i], ciz = s_cz[i];
        float sqi = s_sq[i];

        // lane m<8 holds neighbor vector r_m (others zero -> theta 0, unused)
        float rx = 0.f, ry = 0.f, rz = 0.f;
        if (lane < K) {
            rx = s_rv[rr * (K * 3) + lane * 3 + 0];
            ry = s_rv[rr * (K * 3) + lane * 3 + 1];
            rz = s_rv[rr * (K * 3) + lane * 3 + 2];
        }

        float* outrow = out + (size_t)row * S * H;

        for (int j = warp; j < S; j += 16) {
            float pjx = s_cx[j], pjy = s_cy[j], pjz = s_cz[j];
            float ax = pjx - cix, ay = pjy - ciy, az = pjz - ciz;
            float dist = sqi + s_sq[j] - 2.f * (cix * pjx + ciy * pjy + ciz * pjz);

            // theta for this lane's neighbor (lanes>=8 compute harmless 0)
            float crx = ry * az - rz * ay;
            float cry = rz * ax - rx * az;
            float crz = rx * ay - ry * ax;
            float sn = sqrtf(crx * crx + cry * cry + crz * crz);
            float cs = rx * ax + ry * ay + rz * az;
            float theta = fast_atan2_pos(sn, cs);

            // d-table lookup (global, L2-hot)
            float td = fminf(fmaxf(dist * dscale, 0.f), (float)(NDT - 1));
            int i0 = min((int)td, NDT - 2);
            float fd = td - (float)i0;
            const float2* dr = (const float2*)(g_dtab + (size_t)i0 * H);
            float2 d0 = dr[lane];
            float2 d1 = dr[lane + 32];
            float2 dv;
            dv.x = fmaf(fd, d1.x - d0.x, d0.x);
            dv.y = fmaf(fd, d1.y - d0.y, d0.y);

            // angle table: max over 8 neighbors
            float2 acc;
            acc.x = -3.4e38f; acc.y = -3.4e38f;
#pragma unroll
            for (int m = 0; m < K; m++) {
                float th = __shfl_sync(0xffffffffu, theta, m);
                float ta = th * ascale;
                int ia = min((int)ta, NA - 2);
                float fa = ta - (float)ia;
                const float2* ar = (const float2*)(s_atab + ia * H);
                float2 a0 = ar[lane];
                float2 a1 = ar[lane + 32];
                acc.x = fmaxf(acc.x, fmaf(fa, a1.x - a0.x, a0.x));
                acc.y = fmaxf(acc.y, fmaf(fa, a1.y - a0.y, a0.y));
            }

            float2 o;
            o.x = dv.x + acc.x;
            o.y = dv.y + acc.y;
            ((float2*)(outrow + (size_t)j * H))[lane] = o;
        }
    }
}

// ---------------------------------------------------------------------------
extern "C" void kernel_launch(void* const* d_in, const int* in_sizes, int n_in,
                              void* d_out, int out_size) {
    const float* centroid = (const float*)d_in[0];
    const float* Wd = (const float*)d_in[1];
    const float* bd = (const float*)d_in[2];
    const float* Wa = (const float*)d_in[3];
    const float* ba = (const float*)d_in[4];
    float* out = (float*)d_out;

    static int smem_bytes = (NA * H + 4 * S + 4 * K * 3) * (int)sizeof(float);
    cudaFuncSetAttribute(main_kernel, cudaFuncAttributeMaxDynamicSharedMemorySize,
                         smem_bytes);

    knn_kernel<<<B, S>>>(centroid);
    table_kernel<<<(NDT + NA + 7) / 8, 256>>>(Wd, bd, Wa, ba);
    main_kernel<<<(B * S) / 4, 512, smem_bytes>>>(centroid, out);
}

// round 3
// speedup vs baseline: 2.4728x; 2.4728x over previous
#include <cuda_runtime.h>
#include <math.h>

// Problem shapes (fixed by dataset)
#define B 4
#define S 256
#define C 3
#define H 64
#define K 8

#define NDT 4096    // dist-table rows (global, 2MB w/ deltas, L2-resident)
#define NA  128     // angle-table rows (shared, 64KB w/ deltas)
#define RPC 2       // rows (b,i) per CTA in main kernel
#define PI_F 3.14159265358979323846f

// Scratch (allocation-free: __device__ globals)
__device__ float        g_rv[B * S * K * 3];   // knn relative vectors
__device__ unsigned int g_bmax[B];             // per-batch max sq-dist (float bits)
__device__ float        g_dtab[NDT * 2 * H];   // interleaved (v, dv) per channel
__device__ float        g_atab[NA * 2 * H];    // interleaved (v, dv) per channel

// ---------------------------------------------------------------------------
__global__ void init_kernel() {
    if (threadIdx.x < B) g_bmax[threadIdx.x] = 0u;
}

// ---------------------------------------------------------------------------
// kNN: one warp per point i. Lane l scans j in [8l, 8l+8), keeps a sorted
// top-8 (strict <, increasing j => stable ties like argsort). Then 8 rounds
// of lexicographic warp-argmin produce the global top-8 in order.
// grid = B*32 CTAs x 256 threads (8 warps = 8 points per CTA).
// ---------------------------------------------------------------------------
__global__ __launch_bounds__(256) void knn_kernel(const float* __restrict__ centroid) {
    __shared__ float cx[S], cy[S], cz[S], sq[S];
    int tid = threadIdx.x, lane = tid & 31, warp = tid >> 5;
    int b = blockIdx.x >> 5;

    const float* cb = centroid + (size_t)b * S * 3;
    {
        float x = cb[tid * 3 + 0];
        float y = cb[tid * 3 + 1];
        float z = cb[tid * 3 + 2];
        cx[tid] = x; cy[tid] = y; cz[tid] = z;
        sq[tid] = x * x + y * y + z * z;
    }
    __syncthreads();

    int i = ((blockIdx.x & 31) << 3) + warp;
    float cix = cx[i], ciy = cy[i], ciz = cz[i], sqi = sq[i];

    float bd[K]; int bj[K];
#pragma unroll
    for (int m = 0; m < K; m++) { bd[m] = 3.4e38f; bj[m] = 0x7fffffff; }

    float lmax = 0.f;
#pragma unroll
    for (int t = 0; t < 8; t++) {
        int j = lane * 8 + t;
        float d = sqi + sq[j] - 2.f * (cix * cx[j] + ciy * cy[j] + ciz * cz[j]);
        lmax = fmaxf(lmax, d);
        if (d < bd[K - 1]) {
#pragma unroll
            for (int p = K - 1; p > 0; p--) {
                bool sh = d < bd[p - 1];
                float nd = sh ? bd[p - 1] : d;
                int   nj = sh ? bj[p - 1] : j;
                if (d < bd[p]) { bd[p] = nd; bj[p] = nj; }
            }
            if (d < bd[0]) { bd[0] = d; bj[0] = j; }
        }
    }

    // per-batch max squared distance (float bits monotone for >=0)
#pragma unroll
    for (int off = 16; off > 0; off >>= 1)
        lmax = fmaxf(lmax, __shfl_xor_sync(0xffffffffu, lmax, off));
    if (lane == 0) atomicMax(&g_bmax[b], __float_as_uint(fmaxf(lmax, 0.f)));

    // 8 selection rounds: global lexicographic min of (d, j)
    float hd = bd[0]; int hj = bj[0];
#pragma unroll
    for (int m = 0; m < K; m++) {
        float md = hd; int mj = hj;
#pragma unroll
        for (int off = 16; off > 0; off >>= 1) {
            float od = __shfl_xor_sync(0xffffffffu, md, off);
            int   oj = __shfl_xor_sync(0xffffffffu, mj, off);
            if (od < md || (od == md && oj < mj)) { md = od; mj = oj; }
        }
        if (lane == m) {
            size_t base = ((size_t)(b * S + i)) * (K * 3) + m * 3;
            g_rv[base + 0] = cx[mj] - cix;
            g_rv[base + 1] = cy[mj] - ciy;
            g_rv[base + 2] = cz[mj] - ciz;
        }
        if (hj == mj) {   // unique owner (j values globally unique)
#pragma unroll
            for (int p = 0; p < K - 1; p++) { bd[p] = bd[p + 1]; bj[p] = bj[p + 1]; }
            bd[K - 1] = 3.4e38f; bj[K - 1] = 0x7fffffff;
            hd = bd[0]; hj = bj[0];
        }
    }
}

// ---------------------------------------------------------------------------
// Tables: one warp per row; computes g(x_r) and g(x_{r+1}), stores interleaved
// (value, delta) per channel: row = [v0,dv0,v1,dv1,...,v63,dv63] (512B).
// rows [0, NDT) -> dist table; rows [NDT, NDT+NA) -> angle table.
// ---------------------------------------------------------------------------
__global__ __launch_bounds__(256) void table_kernel(
        const float* __restrict__ Wd, const float* __restrict__ bd_,
        const float* __restrict__ Wa, const float* __restrict__ ba) {
    int lane = threadIdx.x & 31, warp = threadIdx.x >> 5;
    int row = blockIdx.x * 8 + warp;
    if (row >= NDT + NA) return;

    float dmax = fmaxf(fmaxf(__uint_as_float(g_bmax[0]), __uint_as_float(g_bmax[1])),
                       fmaxf(__uint_as_float(g_bmax[2]), __uint_as_float(g_bmax[3])));

    float x0, step;
    const float *W, *bias;
    float* tab;
    if (row < NDT) {
        step = dmax / (float)(NDT - 1);
        x0 = (float)row * step;
        W = Wd; bias = bd_; tab = g_dtab + (size_t)row * 2 * H;
    } else {
        int r = row - NDT;
        step = PI_F / (float)(NA - 1);
        x0 = (float)r * step;
        W = Wa; bias = ba; tab = g_atab + (size_t)r * 2 * H;
    }

    float divf = expf(-0.28782313662425572f * (float)lane);  // exp(-ln1e4/32 * f)
    float s0, c0, s1, c1;
    sincosf(x0 * divf, &s0, &c0);
    sincosf((x0 + step) * divf, &s1, &c1);

    int o0 = 2 * lane, o1 = o0 + 1;
    float a0 = bias[o0], a1 = bias[o1];
    float b0 = a0, b1 = a1;
#pragma unroll
    for (int f = 0; f < 32; f++) {
        float sf0 = __shfl_sync(0xffffffffu, s0, f);
        float cf0 = __shfl_sync(0xffffffffu, c0, f);
        float sf1 = __shfl_sync(0xffffffffu, s1, f);
        float cf1 = __shfl_sync(0xffffffffu, c1, f);
        float w0 = __ldg(&W[o0 * H + 2 * f]);
        float w1 = __ldg(&W[o0 * H + 2 * f + 1]);
        float w2 = __ldg(&W[o1 * H + 2 * f]);
        float w3 = __ldg(&W[o1 * H + 2 * f + 1]);
        a0 = fmaf(sf0, w0, a0); a0 = fmaf(cf0, w1, a0);
        b0 = fmaf(sf1, w0, b0); b0 = fmaf(cf1, w1, b0);
        a1 = fmaf(sf0, w2, a1); a1 = fmaf(cf0, w3, a1);
        b1 = fmaf(sf1, w2, b1); b1 = fmaf(cf1, w3, b1);
    }
    float4 o;
    o.x = a0; o.y = b0 - a0;
    o.z = a1; o.w = b1 - a1;
    ((float4*)tab)[lane] = o;
}

// ---------------------------------------------------------------------------
// fast atan2 for y >= 0, result in [0, pi]. ~1e-6 abs error.
// ---------------------------------------------------------------------------
__device__ __forceinline__ float fast_atan2_pos(float y, float x) {
    float ax = fabsf(x);
    float mn = fminf(ax, y);
    float mx = fmaxf(ax, y);
    float t = __fdividef(mn, fmaxf(mx, 1e-30f));   // 0 when both are 0
    float t2 = t * t;
    float p = fmaf(t2, -0.01172120f, 0.05265332f);
    p = fmaf(t2, p, -0.11643287f);
    p = fmaf(t2, p, 0.19354346f);
    p = fmaf(t2, p, -0.33262347f);
    p = fmaf(t2, p, 0.99997726f);
    float th = t * p;
    th = (y > ax) ? (1.5707963267948966f - th) : th;
    th = (x < 0.f) ? (3.1415926535897931f - th) : th;
    return th;
}

// ---------------------------------------------------------------------------
// Main: 512 CTAs x 256 threads (8 warps), RPC=2 rows per CTA, 3 CTAs/SM.
// a-table (value,delta) in SMEM; single LDS.128 per neighbor lookup;
// d-table via single LDG.128 (L2-hot). Lane owns channels {2l, 2l+1}.
// ---------------------------------------------------------------------------
__global__ __launch_bounds__(256, 3)
void main_kernel(const float* __restrict__ centroid, float* __restrict__ out) {
    extern __shared__ float sm[];
    float* s_atab = sm;                    // NA*2*H = 16384 floats (64KB)
    float* s_cx = sm + NA * 2 * H;         // 256
    float* s_cy = s_cx + S;
    float* s_cz = s_cy + S;
    float* s_sq = s_cz + S;
    float* s_rv = s_sq + S;                // RPC*K*3 = 48

    int tid = threadIdx.x;

    // stage a-table
    {
        float4* dst = (float4*)s_atab;
        const float4* src = (const float4*)g_atab;
#pragma unroll
        for (int idx = tid; idx < (NA * 2 * H) / 4; idx += 256) dst[idx] = src[idx];
    }
    int b = blockIdx.x >> 7;   // 128 CTAs per batch
    {
        const float* cb = centroid + (size_t)b * S * 3;
        float x = cb[tid * 3 + 0];
        float y = cb[tid * 3 + 1];
        float z = cb[tid * 3 + 2];
        s_cx[tid] = x; s_cy[tid] = y; s_cz[tid] = z;
        s_sq[tid] = x * x + y * y + z * z;
        if (tid < RPC * K * 3)
            s_rv[tid] = g_rv[(size_t)blockIdx.x * (RPC * K * 3) + tid];
    }
    float dmax = fmaxf(fmaxf(__uint_as_float(g_bmax[0]), __uint_as_float(g_bmax[1])),
                       fmaxf(__uint_as_float(g_bmax[2]), __uint_as_float(g_bmax[3])));
    float dscale = (float)(NDT - 1) / dmax;
    const float ascale = (float)(NA - 1) / PI_F;
    __syncthreads();

    int warp = tid >> 5, lane = tid & 31;

    for (int rr = 0; rr < RPC; rr++) {
        int row = blockIdx.x * RPC + rr;     // global (b*S+i)
        int i = row & (S - 1);
        float cix = s_cx[i], ciy = s_cy[i], ciz = s_cz[i];
        float sqi = s_sq[i];

        float rx = 0.f, ry = 0.f, rz = 0.f;
        if (lane < K) {
            rx = s_rv[rr * (K * 3) + lane * 3 + 0];
            ry = s_rv[rr * (K * 3) + lane * 3 + 1];
            rz = s_rv[rr * (K * 3) + lane * 3 + 2];
        }

        float* outrow = out + (size_t)row * S * H;

        for (int jt = 0; jt < 32; jt++) {
            int j = warp + jt * 8;
            float pjx = s_cx[j], pjy = s_cy[j], pjz = s_cz[j];
            float ax = pjx - cix, ay = pjy - ciy, az = pjz - ciz;
            float dist = sqi + s_sq[j] - 2.f * (cix * pjx + ciy * pjy + ciz * pjz);

            // d-table lookup: one LDG.128 (v0,dv0,v1,dv1)
            float td = fmaxf(dist * dscale, 0.f);
            int it = (int)td;
            float fd = td - (float)it;
            float4 dq = __ldg(((const float4*)g_dtab) + it * 32 + lane);
            float dv0 = fmaf(fd, dq.y, dq.x);
            float dv1 = fmaf(fd, dq.w, dq.z);

            // theta for this lane's neighbor (lanes>=8: harmless 0)
            float crx = ry * az - rz * ay;
            float cry = rz * ax - rx * az;
            float crz = rx * ay - ry * ax;
            float sn = sqrtf(crx * crx + cry * cry + crz * crz);
            float cs = rx * ax + ry * ay + rz * az;
            float th_s = fast_atan2_pos(sn, cs) * ascale;   // scaled pre-shfl

            // angle table: max over 8 neighbors, one LDS.128 each
            float acc0 = -3.4e38f, acc1 = -3.4e38f;
#pragma unroll
            for (int m = 0; m < K; m++) {
                float ta = __shfl_sync(0xffffffffu, th_s, m);
                int ia = (int)ta;
                float fa = ta - (float)ia;
                float4 aq = *((const float4*)(s_atab + ia * 2 * H) + lane);
                acc0 = fmaxf(acc0, fmaf(fa, aq.y, aq.x));
                acc1 = fmaxf(acc1, fmaf(fa, aq.w, aq.z));
            }

            float2 o;
            o.x = dv0 + acc0;
            o.y = dv1 + acc1;
            ((float2*)(outrow + (size_t)j * H))[lane] = o;
        }
    }
}

// ---------------------------------------------------------------------------
extern "C" void kernel_launch(void* const* d_in, const int* in_sizes, int n_in,
                              void* d_out, int out_size) {
    const float* centroid = (const float*)d_in[0];
    const float* Wd = (const float*)d_in[1];
    const float* bd = (const float*)d_in[2];
    const float* Wa = (const float*)d_in[3];
    const float* ba = (const float*)d_in[4];
    float* out = (float*)d_out;

    int smem_bytes = (NA * 2 * H + 4 * S + RPC * K * 3) * (int)sizeof(float);
    cudaFuncSetAttribute(main_kernel, cudaFuncAttributeMaxDynamicSharedMemorySize,
                         smem_bytes);

    init_kernel<<<1, 32>>>();
    knn_kernel<<<B * 32, 256>>>(centroid);
    table_kernel<<<(NDT + NA + 7) / 8, 256>>>(Wd, bd, Wa, ba);
    main_kernel<<<(B * S) / RPC, 256, smem_bytes>>>(centroid, out);
}

// round 4
// speedup vs baseline: 3.1296x; 1.2656x over previous
#include <cuda_runtime.h>
#include <cuda_fp16.h>
#include <math.h>

// Problem shapes (fixed by dataset)
#define B 4
#define S 256
#define H 64
#define K 8

#define NDT 4096    // dist-table rows, fp32 (v,dv) interleaved, 2MB, L2-resident
#define NA  128     // angle-table rows, fp16 (v,dv) half2-packed, 32KB in smem
#define RPC 2       // (b,i) rows per CTA in main kernel
#define PI_F 3.14159265358979323846f

// Scratch (allocation-free: __device__ globals)
__device__ float  g_rv[B * S * K * 3];   // knn relative vectors
__device__ float  g_pmax[B * 32];        // per-CTA partial max sq-dist (knn grid=128)
__device__ float  g_dmax;                // global max (written by table_kernel)
__device__ float4 g_dtab[NDT * 32];      // row: 32 x float4 {v2c,dv2c,v2c+1,dv2c+1}
__device__ uint4  g_atab[NA * 16];       // row: 256B, per 8B: {h2(v2c,v2c+1), h2(dv2c,dv2c+1)}

__device__ __forceinline__ __half2 u2h(unsigned u) {
    return *reinterpret_cast<__half2*>(&u);
}
__device__ __forceinline__ unsigned h2u(__half2 h) {
    return *reinterpret_cast<unsigned*>(&h);
}

// ---------------------------------------------------------------------------
// kNN: one warp per point i. Lane l scans j in [8l, 8l+8), keeps a sorted
// top-8 (strict <, increasing j => stable ties == argsort). 8 rounds of
// lexicographic warp-argmin produce the global ordered top-8.
// grid = B*32 CTAs x 256 threads. Also writes per-CTA max sq-dist.
// ---------------------------------------------------------------------------
__global__ __launch_bounds__(256) void knn_kernel(const float* __restrict__ centroid) {
    __shared__ float cx[S], cy[S], cz[S], sq[S];
    __shared__ float redmax[8];
    int tid = threadIdx.x, lane = tid & 31, warp = tid >> 5;
    int b = blockIdx.x >> 5;

    const float* cb = centroid + (size_t)b * S * 3;
    {
        float x = cb[tid * 3 + 0];
        float y = cb[tid * 3 + 1];
        float z = cb[tid * 3 + 2];
        cx[tid] = x; cy[tid] = y; cz[tid] = z;
        sq[tid] = x * x + y * y + z * z;
    }
    __syncthreads();

    int i = ((blockIdx.x & 31) << 3) + warp;
    float cix = cx[i], ciy = cy[i], ciz = cz[i], sqi = sq[i];

    float bd[K]; int bj[K];
#pragma unroll
    for (int m = 0; m < K; m++) { bd[m] = 3.4e38f; bj[m] = 0x7fffffff; }

    float lmax = 0.f;
#pragma unroll
    for (int t = 0; t < 8; t++) {
        int j = lane * 8 + t;
        float d = sqi + sq[j] - 2.f * (cix * cx[j] + ciy * cy[j] + ciz * cz[j]);
        lmax = fmaxf(lmax, d);
        if (d < bd[K - 1]) {
#pragma unroll
            for (int p = K - 1; p > 0; p--) {
                bool sh = d < bd[p - 1];
                float nd = sh ? bd[p - 1] : d;
                int   nj = sh ? bj[p - 1] : j;
                if (d < bd[p]) { bd[p] = nd; bj[p] = nj; }
            }
            if (d < bd[0]) { bd[0] = d; bj[0] = j; }
        }
    }

    // per-CTA max squared distance
#pragma unroll
    for (int off = 16; off > 0; off >>= 1)
        lmax = fmaxf(lmax, __shfl_xor_sync(0xffffffffu, lmax, off));
    if (lane == 0) redmax[warp] = lmax;
    __syncthreads();
    if (warp == 0) {
        float v = (lane < 8) ? redmax[lane] : 0.f;
#pragma unroll
        for (int off = 4; off > 0; off >>= 1)
            v = fmaxf(v, __shfl_xor_sync(0xffffffffu, v, off));
        if (lane == 0) g_pmax[blockIdx.x] = fmaxf(v, 0.f);
    }

    // 8 selection rounds: global lexicographic min of (d, j)
    float hd = bd[0]; int hj = bj[0];
#pragma unroll
    for (int m = 0; m < K; m++) {
        float md = hd; int mj = hj;
#pragma unroll
        for (int off = 16; off > 0; off >>= 1) {
            float od = __shfl_xor_sync(0xffffffffu, md, off);
            int   oj = __shfl_xor_sync(0xffffffffu, mj, off);
            if (od < md || (od == md && oj < mj)) { md = od; mj = oj; }
        }
        if (lane == m) {
            size_t base = ((size_t)(b * S + i)) * (K * 3) + m * 3;
            g_rv[base + 0] = cx[mj] - cix;
            g_rv[base + 1] = cy[mj] - ciy;
            g_rv[base + 2] = cz[mj] - ciz;
        }
        if (hj == mj) {   // unique owner (j unique across lanes)
#pragma unroll
            for (int p = 0; p < K - 1; p++) { bd[p] = bd[p + 1]; bj[p] = bj[p + 1]; }
            bd[K - 1] = 3.4e38f; bj[K - 1] = 0x7fffffff;
            hd = bd[0]; hj = bj[0];
        }
    }
}

// ---------------------------------------------------------------------------
// Tables: one warp per row. Reduces g_pmax -> dmax, publishes g_dmax.
// rows [0, NDT)       -> fp32 dist table {v,dv} interleaved
// rows [NDT, NDT+NA)  -> fp16 angle table half2-packed
// grid = (NDT+NA)/8 = 528 CTAs x 256 threads.
// ---------------------------------------------------------------------------
__global__ __launch_bounds__(256) void table_kernel(
        const float* __restrict__ Wd, const float* __restrict__ bd_,
        const float* __restrict__ Wa, const float* __restrict__ ba) {
    int lane = threadIdx.x & 31, warp = threadIdx.x >> 5;
    int row = blockIdx.x * 8 + warp;

    // reduce the 128 partial maxima (cheap, per-warp)
    float v = fmaxf(fmaxf(g_pmax[lane], g_pmax[lane + 32]),
                    fmaxf(g_pmax[lane + 64], g_pmax[lane + 96]));
#pragma unroll
    for (int off = 16; off > 0; off >>= 1)
        v = fmaxf(v, __shfl_xor_sync(0xffffffffu, v, off));
    float dmax = v;
    if (row == 0 && lane == 0) g_dmax = dmax;

    float x0, step;
    const float *W, *bias;
    if (row < NDT) {
        step = dmax / (float)(NDT - 1);
        x0 = (float)row * step;
        W = Wd; bias = bd_;
    } else {
        step = PI_F / (float)(NA - 1);
        x0 = (float)(row - NDT) * step;
        W = Wa; bias = ba;
    }

    float divf = expf(-0.28782313662425572f * (float)lane);  // exp(-ln(1e4)/32 * f)
    float s0, c0, s1, c1;
    sincosf(x0 * divf, &s0, &c0);
    sincosf((x0 + step) * divf, &s1, &c1);

    int o0 = 2 * lane, o1 = o0 + 1;
    float a0 = bias[o0], a1 = bias[o1];
    float b0 = a0, b1 = a1;
#pragma unroll
    for (int f = 0; f < 32; f++) {
        float sf0 = __shfl_sync(0xffffffffu, s0, f);
        float cf0 = __shfl_sync(0xffffffffu, c0, f);
        float sf1 = __shfl_sync(0xffffffffu, s1, f);
        float cf1 = __shfl_sync(0xffffffffu, c1, f);
        float w0 = __ldg(&W[o0 * H + 2 * f]);
        float w1 = __ldg(&W[o0 * H + 2 * f + 1]);
        float w2 = __ldg(&W[o1 * H + 2 * f]);
        float w3 = __ldg(&W[o1 * H + 2 * f + 1]);
        a0 = fmaf(sf0, w0, a0); a0 = fmaf(cf0, w1, a0);
        b0 = fmaf(sf1, w0, b0); b0 = fmaf(cf1, w1, b0);
        a1 = fmaf(sf0, w2, a1); a1 = fmaf(cf0, w3, a1);
        b1 = fmaf(sf1, w2, b1); b1 = fmaf(cf1, w3, b1);
    }

    if (row < NDT) {
        float4 o;
        o.x = a0; o.y = b0 - a0;
        o.z = a1; o.w = b1 - a1;
        g_dtab[row * 32 + lane] = o;
    } else {
        int r = row - NDT;
        __half2 v01 = __floats2half2_rn(a0, a1);
        __half2 d01 = __floats2half2_rn(b0 - a0, b1 - a1);
        uint2 o; o.x = h2u(v01); o.y = h2u(d01);
        ((uint2*)g_atab)[r * 32 + lane] = o;
    }
}

// ---------------------------------------------------------------------------
// fast atan2 for y >= 0, result in [0, pi]. ~1e-6 abs error.
// ---------------------------------------------------------------------------
__device__ __forceinline__ float fast_atan2_pos(float y, float x) {
    float ax = fabsf(x);
    float mn = fminf(ax, y);
    float mx = fmaxf(ax, y);
    float t = __fdividef(mn, fmaxf(mx, 1e-30f));   // 0 when both are 0
    float t2 = t * t;
    float p = fmaf(t2, -0.01172120f, 0.05265332f);
    p = fmaf(t2, p, -0.11643287f);
    p = fmaf(t2, p, 0.19354346f);
    p = fmaf(t2, p, -0.33262347f);
    p = fmaf(t2, p, 0.99997726f);
    float th = t * p;
    th = (y > ax) ? (1.5707963267948966f - th) : th;
    th = (x < 0.f) ? (3.1415926535897931f - th) : th;
    return th;
}

// ---------------------------------------------------------------------------
// Main: 512 CTAs x 256 threads, RPC=2 rows/CTA, 4 CTAs/SM (static 36KB smem).
// Per warp: blocks of 4 j. Lane = (group g = lane>>3, neighbor m = lane&7):
// theta computed once per 4 j. Then 2 pair-steps; each half-warp (16 lanes,
// 4 channels/lane) covers one j: one LDS.128 + 2 HFMA2 + 2 HMAX2 per neighbor
// per 2 j. d-table fp32 via 2x LDG.128. Coalesced STG.128.
// ---------------------------------------------------------------------------
__global__ __launch_bounds__(256, 4)
void main_kernel(const float* __restrict__ centroid, float* __restrict__ out) {
    __shared__ uint4  s_atab[NA * 16];   // 32KB
    __shared__ float4 s_pt[S];           // 4KB  (x,y,z,sq)
    __shared__ float  s_rv[RPC * K * 3];

    int tid = threadIdx.x;

    // stage a-table (32KB)
#pragma unroll
    for (int idx = tid; idx < NA * 16; idx += 256) s_atab[idx] = g_atab[idx];

    int b = blockIdx.x >> 7;   // 128 CTAs per batch
    {
        const float* cb = centroid + (size_t)b * S * 3;
        float x = cb[tid * 3 + 0];
        float y = cb[tid * 3 + 1];
        float z = cb[tid * 3 + 2];
        float4 p; p.x = x; p.y = y; p.z = z; p.w = x * x + y * y + z * z;
        s_pt[tid] = p;
        if (tid < RPC * K * 3)
            s_rv[tid] = g_rv[(size_t)blockIdx.x * (RPC * K * 3) + tid];
    }
    float dscale = (float)(NDT - 1) / g_dmax;
    const float ascale = (float)(NA - 1) / PI_F;
    __syncthreads();

    int warp = tid >> 5, lane = tid & 31;
    int g = lane >> 3, m = lane & 7;
    int lane16 = lane & 15, jsel = lane >> 4;

    for (int rr = 0; rr < RPC; rr++) {
        int row = blockIdx.x * RPC + rr;     // global (b*S+i)
        int i = row & (S - 1);
        float4 pi = s_pt[i];

        float rx = s_rv[rr * (K * 3) + m * 3 + 0];
        float ry = s_rv[rr * (K * 3) + m * 3 + 1];
        float rz = s_rv[rr * (K * 3) + m * 3 + 2];

        float4* outp = (float4*)out + (size_t)row * S * (H / 4);

        for (int t = 0; t < 8; t++) {
            int jb = (t * 8 + warp) * 4;

            // group g handles j = jb+g; neighbor m's theta for that j
            float4 pj = s_pt[jb + g];
            float ax = pj.x - pi.x, ay = pj.y - pi.y, az = pj.z - pi.z;
            float dist_g = pi.w + pj.w
                         - 2.f * (pi.x * pj.x + pi.y * pj.y + pi.z * pj.z);

            float crx = ry * az - rz * ay;
            float cry = rz * ax - rx * az;
            float crz = rx * ay - ry * ax;
            float ss = crx * crx + cry * cry + crz * crz;
            float sn = ss * rsqrtf(fmaxf(ss, 1e-35f));   // 0 when ss==0
            float cs = rx * ax + ry * ay + rz * az;
            float th_s = fast_atan2_pos(sn, cs) * ascale;

#pragma unroll
            for (int p = 0; p < 2; p++) {
                int src = (2 * p + jsel) << 3;      // source group base lane
                float dist = __shfl_sync(0xffffffffu, dist_g, src);

                // d-table: fp32, two LDG.128 per lane (4 channels)
                float td = fmaxf(dist * dscale, 0.f);
                int it = min((int)td, NDT - 1);
                float fd = td - (float)it;
                const float4* drow = g_dtab + it * 32 + 2 * lane16;
                float4 dq0 = __ldg(drow);
                float4 dq1 = __ldg(drow + 1);
                float d0 = fmaf(fd, dq0.y, dq0.x);
                float d1 = fmaf(fd, dq0.w, dq0.z);
                float d2 = fmaf(fd, dq1.y, dq1.x);
                float d3 = fmaf(fd, dq1.w, dq1.z);

                // a-table: fp16 half2, max over 8 neighbors
                __half2 acc01 = __float2half2_rn(-60000.f);
                __half2 acc23 = acc01;
#pragma unroll
                for (int mm = 0; mm < 8; mm++) {
                    float ta = __shfl_sync(0xffffffffu, th_s, src + mm);
                    int ia = min((int)ta, NA - 1);
                    __half2 fa2 = __float2half2_rn(ta - (float)ia);
                    uint4 aq = s_atab[ia * 16 + lane16];
                    acc01 = __hmax2(acc01, __hfma2(fa2, u2h(aq.y), u2h(aq.x)));
                    acc23 = __hmax2(acc23, __hfma2(fa2, u2h(aq.w), u2h(aq.z)));
                }
                float2 a01 = __half22float2(acc01);
                float2 a23 = __half22float2(acc23);

                float4 o;
                o.x = d0 + a01.x;
                o.y = d1 + a01.y;
                o.z = d2 + a23.x;
                o.w = d3 + a23.y;
                int j = jb + 2 * p + jsel;
                outp[j * (H / 4) + lane16] = o;
            }
        }
    }
}

// ---------------------------------------------------------------------------
extern "C" void kernel_launch(void* const* d_in, const int* in_sizes, int n_in,
                              void* d_out, int out_size) {
    const float* centroid = (const float*)d_in[0];
    const float* Wd = (const float*)d_in[1];
    const float* bd = (const float*)d_in[2];
    const float* Wa = (const float*)d_in[3];
    const float* ba = (const float*)d_in[4];
    float* out = (float*)d_out;

    knn_kernel<<<B * 32, 256>>>(centroid);
    table_kernel<<<(NDT + NA) / 8, 256>>>(Wd, bd, Wa, ba);
    main_kernel<<<(B * S) / RPC, 256>>>(centroid, out);
}